// round 14
// baseline (speedup 1.0000x reference)
#include <cuda_runtime.h>
#include <math.h>

#define BB 2
#define LL 2048
#define HID 2048
#define NH 16
#define KVH 4
#define DD 128
#define HD 2048
#define KVD 512
#define WIN 1024

// ---------------- scratch (device globals: no allocation allowed) ----------
__device__ float g_q[BB*LL*HD];
__device__ float g_k[BB*LL*KVD];
__device__ float g_v[BB*LL*KVD];
__device__ float g_o[BB*LL*HD];
__device__ int   g_rank[BB*LL];
__device__ float g_invf[64];

// ---------------- inv_freq precompute (accurate, double pow) ---------------
__global__ void invf_kernel() {
    int i = threadIdx.x;
    g_invf[i] = (float)pow(10000.0, -(double)i / 64.0);
}

// ---------------- SGEMM: C[M,N] = A[M,K] @ W[N,K]^T  (M%128==0,N%128==0,K%8==0)
__global__ __launch_bounds__(256, 2) void sgemm_nt(
    const float* __restrict__ A, const float* __restrict__ W,
    float* __restrict__ C, int M, int N, int K)
{
    __shared__ float AsT[8][128];
    __shared__ float WsT[8][128];
    int t  = threadIdx.x;
    int tx = t & 15, ty = t >> 4;
    int bx = blockIdx.x, by = blockIdx.y;
    int lr = t >> 1;
    int lk = (t & 1) * 4;
    const float* Aptr = A + (size_t)(by*128 + lr)*K + lk;
    const float* Wptr = W + (size_t)(bx*128 + lr)*K + lk;

    float acc[8][8];
    #pragma unroll
    for (int i = 0; i < 8; i++)
        #pragma unroll
        for (int j = 0; j < 8; j++) acc[i][j] = 0.f;

    int nk = K >> 3;
    for (int kt = 0; kt < nk; kt++) {
        float4 ra = *(const float4*)(Aptr + (size_t)kt*8);
        float4 rw = *(const float4*)(Wptr + (size_t)kt*8);
        __syncthreads();
        AsT[lk+0][lr] = ra.x; AsT[lk+1][lr] = ra.y;
        AsT[lk+2][lr] = ra.z; AsT[lk+3][lr] = ra.w;
        WsT[lk+0][lr] = rw.x; WsT[lk+1][lr] = rw.y;
        WsT[lk+2][lr] = rw.z; WsT[lk+3][lr] = rw.w;
        __syncthreads();
        #pragma unroll
        for (int k = 0; k < 8; k++) {
            float4 a0 = *(const float4*)&AsT[k][ty*8];
            float4 a1 = *(const float4*)&AsT[k][ty*8+4];
            float4 b0 = *(const float4*)&WsT[k][tx*8];
            float4 b1 = *(const float4*)&WsT[k][tx*8+4];
            float av[8] = {a0.x,a0.y,a0.z,a0.w,a1.x,a1.y,a1.z,a1.w};
            float bv[8] = {b0.x,b0.y,b0.z,b0.w,b1.x,b1.y,b1.z,b1.w};
            #pragma unroll
            for (int i = 0; i < 8; i++)
                #pragma unroll
                for (int j = 0; j < 8; j++)
                    acc[i][j] = fmaf(av[i], bv[j], acc[i][j]);
        }
    }
    #pragma unroll
    for (int i = 0; i < 8; i++) {
        float* cp = C + (size_t)(by*128 + ty*8 + i)*N + bx*128 + tx*8;
        *(float4*)(cp)   = make_float4(acc[i][0],acc[i][1],acc[i][2],acc[i][3]);
        *(float4*)(cp+4) = make_float4(acc[i][4],acc[i][5],acc[i][6],acc[i][7]);
    }
}

// ---------------- RoPE (in place on q and k) --------------------------------
// NOTE: sincosf writes SIN to the first pointer, COS to the second.
__global__ void rope_kernel(float* __restrict__ q, float* __restrict__ k,
                            const int* __restrict__ pos)
{
    int idx = blockIdx.x * 256 + threadIdx.x;
    if (idx >= BB*LL*(NH+KVH)*64) return;
    int i    = idx & 63;
    int rest = idx >> 6;
    int head = rest % (NH+KVH);
    int bl   = rest / (NH+KVH);
    float p   = (float)pos[bl];
    float ang = p * g_invf[i];
    float r   = (float)fmod((double)ang, 6.283185307179586); // keep fast-math sincos accurate
    float s, c;
    sincosf(r, &s, &c);          // FIXED: sin first, cos second
    float* ptr = (head < NH) ? (q + ((size_t)bl*NH + head)*DD)
                             : (k + ((size_t)bl*KVH + (head-NH))*DD);
    float x1 = ptr[i], x2 = ptr[i+64];
    ptr[i]    = x1*c - x2*s;
    ptr[i+64] = x2*c + x1*s;
}

// ---------------- per-position rank within its state ------------------------
__global__ void rank_kernel(const int* __restrict__ sid, int* __restrict__ rank)
{
    __shared__ int s[LL];
    int b = blockIdx.x, t = threadIdx.x;
    s[t]        = sid[(size_t)b*LL + t];
    s[t + 1024] = sid[(size_t)b*LL + t + 1024];
    __syncthreads();
    int l1 = t, l2 = t + 1024;
    int me1 = s[l1], me2 = s[l2];
    int c1 = 0, c2 = 0;
    for (int j = 0; j < LL; j++) {
        int sj = s[j];
        c1 += (j <= l1 && sj == me1);
        c2 += (j <= l2 && sj == me2);
    }
    rank[(size_t)b*LL + l1] = c1 - 1;
    rank[(size_t)b*LL + l2] = c2 - 1;
}

// ---------------- flash attention: 64 q-rows x 64-key tiles -----------------
// smem words: QsT 128*68 + KVs 128*68 + Ss 64*65 + 3*64 + 4*64 = 22016 (88064 B)
#define ATTN_SMEM_BYTES 88064

__global__ __launch_bounds__(256, 2) void attn_kernel(
    const float* __restrict__ q, const float* __restrict__ k,
    const float* __restrict__ v, const int* __restrict__ sid,
    const int* __restrict__ rank, float* __restrict__ o)
{
    extern __shared__ float sm[];
    float* QsT   = sm;                   // [128][68] transposed Q tile (scaled)
    float* KVs   = sm + 128*68;          // K as [128][68] transposed, then V as [64][128]
    float* Ss    = KVs + 128*68;         // [64][65] scores / probs
    float* m_s   = Ss + 64*65;
    float* l_s   = m_s + 64;
    float* fac_s = l_s + 64;
    int* sidq  = (int*)(fac_s + 64);
    int* rankq = sidq + 64;
    int* sidk  = rankq + 64;
    int* rankk = sidk + 64;

    int qt = blockIdx.x, h = blockIdx.y, b = blockIdx.z;
    int kvh  = h >> 2;
    int tid  = threadIdx.x;
    int lane = tid & 31, wid = tid >> 5;
    int tx   = tid & 15, ty  = tid >> 4;
    int q0   = qt * 64;

    const float* qbase = q + ((size_t)(b*LL + q0)*NH + h)*DD;
    for (int i = tid; i < 64*128; i += 256) {
        int r = i >> 7, d = i & 127;
        QsT[d*68 + r] = qbase[(size_t)r*HD + d] * 0.08838834764831845f;
    }
    if (tid < 64) {
        m_s[tid] = -1e30f; l_s[tid] = 0.f;
        sidq[tid]  = sid[(size_t)b*LL + q0 + tid];
        rankq[tid] = rank[(size_t)b*LL + q0 + tid];
    }
    float o_acc[4][8];
    #pragma unroll
    for (int i = 0; i < 4; i++)
        #pragma unroll
        for (int c = 0; c < 8; c++) o_acc[i][c] = 0.f;

    for (int kt = 0; kt <= qt; kt++) {
        int k0 = kt * 64;
        __syncthreads();  // previous PV done before overwriting KVs / Ss
        const float* kbase = k + ((size_t)(b*LL + k0)*KVH + kvh)*DD;
        for (int i = tid; i < 64*128; i += 256) {
            int r = i >> 7, d = i & 127;
            KVs[d*68 + r] = kbase[(size_t)r*KVD + d];
        }
        if (tid < 64) {
            sidk[tid]  = sid[(size_t)b*LL + k0 + tid];
            rankk[tid] = rank[(size_t)b*LL + k0 + tid];
        }
        __syncthreads();

        // S = (Q*scale) @ K^T : 4x4 per thread over 64x64 tile
        float acc[4][4];
        #pragma unroll
        for (int i = 0; i < 4; i++)
            #pragma unroll
            for (int j = 0; j < 4; j++) acc[i][j] = 0.f;
        #pragma unroll 8
        for (int d = 0; d < 128; d++) {
            float4 a  = *(const float4*)(QsT + d*68 + ty*4);
            float4 bb = *(const float4*)(KVs + d*68 + tx*4);
            float av[4] = {a.x, a.y, a.z, a.w};
            float bv[4] = {bb.x, bb.y, bb.z, bb.w};
            #pragma unroll
            for (int i = 0; i < 4; i++)
                #pragma unroll
                for (int j = 0; j < 4; j++)
                    acc[i][j] = fmaf(av[i], bv[j], acc[i][j]);
        }
        // mask + stage to shared
        #pragma unroll
        for (int i = 0; i < 4; i++) {
            int qi = ty*4 + i;
            #pragma unroll
            for (int j = 0; j < 4; j++) {
                int kj = tx*4 + j;
                bool ok = (k0 + kj <= q0 + qi) && (sidk[kj] == sidq[qi])
                          && (rankq[qi] - rankk[kj] <= WIN);
                Ss[qi*65 + kj] = ok ? acc[i][j] : -1e30f;
            }
        }
        __syncthreads();

        // online softmax: warp wid owns rows wid*8 .. +7
        #pragma unroll
        for (int rr = 0; rr < 8; rr++) {
            int r = wid*8 + rr;
            float s1 = Ss[r*65 + lane];
            float s2 = Ss[r*65 + 32 + lane];
            float mx = fmaxf(s1, s2);
            #pragma unroll
            for (int off = 16; off > 0; off >>= 1)
                mx = fmaxf(mx, __shfl_xor_sync(0xffffffffu, mx, off));
            float mold = m_s[r];
            float mnew = fmaxf(mold, mx);
            float p1 = (s1 > -1e29f) ? __expf(s1 - mnew) : 0.f;
            float p2 = (s2 > -1e29f) ? __expf(s2 - mnew) : 0.f;
            Ss[r*65 + lane]      = p1;
            Ss[r*65 + 32 + lane] = p2;
            float sum = p1 + p2;
            #pragma unroll
            for (int off = 16; off > 0; off >>= 1)
                sum += __shfl_xor_sync(0xffffffffu, sum, off);
            if (lane == 0) {
                float f = __expf(mold - mnew);
                fac_s[r] = f;
                m_s[r]   = mnew;
                l_s[r]   = l_s[r]*f + sum;
            }
        }
        // load V over the K buffer (K reads all completed before prior sync)
        const float* vbase = v + ((size_t)(b*LL + k0)*KVH + kvh)*DD;
        for (int i = tid; i < 64*128; i += 256)
            KVs[i] = vbase[(size_t)(i >> 7)*KVD + (i & 127)];
        __syncthreads();

        // rescale accumulators, then O += P @ V
        #pragma unroll
        for (int i = 0; i < 4; i++) {
            float f = fac_s[ty*4 + i];
            #pragma unroll
            for (int c = 0; c < 8; c++) o_acc[i][c] *= f;
        }
        #pragma unroll 2
        for (int j = 0; j < 64; j++) {
            float av[4];
            #pragma unroll
            for (int i = 0; i < 4; i++) av[i] = Ss[(ty*4 + i)*65 + j];
            float4 v0 = *(const float4*)(KVs + j*128 + tx*8);
            float4 v1 = *(const float4*)(KVs + j*128 + tx*8 + 4);
            float bv[8] = {v0.x,v0.y,v0.z,v0.w,v1.x,v1.y,v1.z,v1.w};
            #pragma unroll
            for (int i = 0; i < 4; i++)
                #pragma unroll
                for (int c = 0; c < 8; c++)
                    o_acc[i][c] = fmaf(av[i], bv[c], o_acc[i][c]);
        }
    }

    float* obase = o + ((size_t)(b*LL + q0)*NH + h)*DD;
    #pragma unroll
    for (int i = 0; i < 4; i++) {
        int r = ty*4 + i;
        float invl = 1.0f / l_s[r];
        float* cp = obase + (size_t)r*HD + tx*8;
        #pragma unroll
        for (int c = 0; c < 8; c++) cp[c] = o_acc[i][c] * invl;
    }
}

// ---------------- launch ----------------------------------------------------
extern "C" void kernel_launch(void* const* d_in, const int* in_sizes, int n_in,
                              void* d_out, int out_size)
{
    const float* hs = (const float*)d_in[0];
    const float* Wq = (const float*)d_in[1];
    const float* Wk = (const float*)d_in[2];
    const float* Wv = (const float*)d_in[3];
    const float* Wo = (const float*)d_in[4];
    const int*   sid = (const int*)d_in[5];   // confirmed int32 by round-13 dump
    const int*   pos = (const int*)d_in[6];   // confirmed int32 by round-13 dump
    float* out = (float*)d_out;

    float *qp, *kp, *vp, *op;
    int* rp;
    cudaGetSymbolAddress((void**)&qp, g_q);
    cudaGetSymbolAddress((void**)&kp, g_k);
    cudaGetSymbolAddress((void**)&vp, g_v);
    cudaGetSymbolAddress((void**)&op, g_o);
    cudaGetSymbolAddress((void**)&rp, g_rank);

    cudaFuncSetAttribute(attn_kernel, cudaFuncAttributeMaxDynamicSharedMemorySize,
                         ATTN_SMEM_BYTES);

    invf_kernel<<<1, 64>>>();
    sgemm_nt<<<dim3(HD/128,  (BB*LL)/128), 256>>>(hs, Wq, qp, BB*LL, HD,  HID);
    sgemm_nt<<<dim3(KVD/128, (BB*LL)/128), 256>>>(hs, Wk, kp, BB*LL, KVD, HID);
    sgemm_nt<<<dim3(KVD/128, (BB*LL)/128), 256>>>(hs, Wv, vp, BB*LL, KVD, HID);

    int nrope = BB*LL*(NH+KVH)*64;
    rope_kernel<<<(nrope + 255)/256, 256>>>(qp, kp, pos);
    rank_kernel<<<BB, 1024>>>(sid, rp);

    attn_kernel<<<dim3(LL/64, NH, BB), 256, ATTN_SMEM_BYTES>>>(qp, kp, vp, sid, rp, op);

    sgemm_nt<<<dim3(HID/128, (BB*LL)/128), 256>>>(op, Wo, out, BB*LL, HID, HID);
}

// round 15
// speedup vs baseline: 1.5062x; 1.5062x over previous
#include <cuda_runtime.h>
#include <math.h>
#include <stdint.h>

#define BB 2
#define LL 2048
#define HID 2048
#define NH 16
#define KVH 4
#define DD 128
#define HD 2048
#define KVD 512
#define WIN 1024

// ---------------- scratch (device globals: no allocation allowed) ----------
__device__ float g_q[BB*LL*HD];
__device__ float g_k[BB*LL*KVD];
__device__ float g_v[BB*LL*KVD];
__device__ float g_o[BB*LL*HD];
__device__ int   g_rank[BB*LL];
__device__ float g_invf[64];

// ---------------- inv_freq precompute ---------------------------------------
__global__ void invf_kernel() {
    int i = threadIdx.x;
    g_invf[i] = (float)pow(10000.0, -(double)i / 64.0);
}

// ---------------- tf32 tensor-core GEMM: C[M,N] = A[M,K] @ W[N,K]^T ---------
// Block 128x128, 8 warps (4M x 2N), warp tile 32x64, K-chunk 16, 4-stage cp.async.
#define GSTAGES 4
#define GCHUNK  16
#define GSTRIDE 20                      // floats per smem row (16 + 4 pad)
#define GSTAGE_FLOATS (2 * 128 * GSTRIDE)   // A tile + W tile
#define GEMM_SMEM_BYTES (GSTAGES * GSTAGE_FLOATS * 4)

__device__ __forceinline__ uint32_t f2tf(float x) {
    uint32_t u;
    asm volatile("cvt.rna.tf32.f32 %0, %1;" : "=r"(u) : "f"(x));
    return u;
}
__device__ __forceinline__ void mma_tf32(float* d, const uint32_t* a,
                                         uint32_t b0, uint32_t b1) {
    asm volatile(
        "mma.sync.aligned.m16n8k8.row.col.f32.tf32.tf32.f32 "
        "{%0,%1,%2,%3}, {%4,%5,%6,%7}, {%8,%9}, {%0,%1,%2,%3};"
        : "+f"(d[0]), "+f"(d[1]), "+f"(d[2]), "+f"(d[3])
        : "r"(a[0]), "r"(a[1]), "r"(a[2]), "r"(a[3]), "r"(b0), "r"(b1));
}
__device__ __forceinline__ void cp16(uint32_t dst, const void* src) {
    asm volatile("cp.async.ca.shared.global [%0], [%1], 16;" :: "r"(dst), "l"(src));
}

__global__ __launch_bounds__(256) void gemm_tf32(
    const float* __restrict__ A, const float* __restrict__ W,
    float* __restrict__ C, int M, int N, int K)
{
    extern __shared__ float sm[];
    int t = threadIdx.x;
    int lane = t & 31, warp = t >> 5;
    int warpM = warp & 3, warpN = warp >> 2;   // 4 x 2
    int gid = lane >> 2, tig = lane & 3;
    int row0 = blockIdx.y * 128, col0 = blockIdx.x * 128;

    // global->smem mapping: thread loads one row-half (16B x2) per matrix
    int lrow = t >> 1;
    int lk   = (t & 1) * 8;
    const float* Ag = A + (size_t)(row0 + lrow)*K + lk;
    const float* Wg = W + (size_t)(col0 + lrow)*K + lk;
    uint32_t smem_base;
    {
        void* p = sm;
        smem_base = (uint32_t)__cvta_generic_to_shared(p);
    }
    uint32_t a_dst0 = smem_base + (uint32_t)(lrow*GSTRIDE + lk) * 4;
    uint32_t w_dst0 = a_dst0 + 128*GSTRIDE*4;

    float acc[2][8][4];
    #pragma unroll
    for (int mt = 0; mt < 2; mt++)
        #pragma unroll
        for (int nt = 0; nt < 8; nt++)
            #pragma unroll
            for (int c = 0; c < 4; c++) acc[mt][nt][c] = 0.f;

    int NK = K / GCHUNK;

    // prologue: stages 0..2
    #pragma unroll
    for (int s = 0; s < GSTAGES - 1; s++) {
        uint32_t off = (uint32_t)(s * GSTAGE_FLOATS * 4);
        const float* ag = Ag + (size_t)s * GCHUNK;
        const float* wg = Wg + (size_t)s * GCHUNK;
        cp16(a_dst0 + off,      ag);
        cp16(a_dst0 + off + 16, ag + 4);
        cp16(w_dst0 + off,      wg);
        cp16(w_dst0 + off + 16, wg + 4);
        asm volatile("cp.async.commit_group;");
    }

    for (int kt = 0; kt < NK; kt++) {
        asm volatile("cp.async.wait_group %0;" :: "n"(GSTAGES - 2));
        __syncthreads();

        int s = kt & (GSTAGES - 1);
        const float* As = sm + s * GSTAGE_FLOATS;
        const float* Ws = As + 128*GSTRIDE;

        // issue chunk kt+3 into stage (kt+3)&3 (safe: sync above closed kt-1)
        int kn = kt + GSTAGES - 1;
        if (kn < NK) {
            uint32_t off = (uint32_t)((kn & (GSTAGES-1)) * GSTAGE_FLOATS * 4);
            const float* ag = Ag + (size_t)kn * GCHUNK;
            const float* wg = Wg + (size_t)kn * GCHUNK;
            cp16(a_dst0 + off,      ag);
            cp16(a_dst0 + off + 16, ag + 4);
            cp16(w_dst0 + off,      wg);
            cp16(w_dst0 + off + 16, wg + 4);
            asm volatile("cp.async.commit_group;");
        }

        #pragma unroll
        for (int g = 0; g < 2; g++) {
            uint32_t afr[2][4];
            #pragma unroll
            for (int mt = 0; mt < 2; mt++) {
                const float* ab = As + (warpM*32 + mt*16 + gid)*GSTRIDE + g*8;
                afr[mt][0] = f2tf(ab[tig]);
                afr[mt][1] = f2tf(ab[8*GSTRIDE + tig]);
                afr[mt][2] = f2tf(ab[tig + 4]);
                afr[mt][3] = f2tf(ab[8*GSTRIDE + tig + 4]);
            }
            #pragma unroll
            for (int nt = 0; nt < 8; nt++) {
                const float* bb = Ws + (warpN*64 + nt*8 + gid)*GSTRIDE + g*8;
                uint32_t b0 = f2tf(bb[tig]);
                uint32_t b1 = f2tf(bb[tig + 4]);
                mma_tf32(acc[0][nt], afr[0], b0, b1);
                mma_tf32(acc[1][nt], afr[1], b0, b1);
            }
        }
    }

    // epilogue
    #pragma unroll
    for (int mt = 0; mt < 2; mt++) {
        int r = row0 + warpM*32 + mt*16 + gid;
        #pragma unroll
        for (int nt = 0; nt < 8; nt++) {
            int c = col0 + warpN*64 + nt*8 + tig*2;
            *(float2*)(C + (size_t)r*N + c) =
                make_float2(acc[mt][nt][0], acc[mt][nt][1]);
            *(float2*)(C + (size_t)(r+8)*N + c) =
                make_float2(acc[mt][nt][2], acc[mt][nt][3]);
        }
    }
}

// ---------------- RoPE (in place on q and k) --------------------------------
__global__ void rope_kernel(float* __restrict__ q, float* __restrict__ k,
                            const int* __restrict__ pos)
{
    int idx = blockIdx.x * 256 + threadIdx.x;
    if (idx >= BB*LL*(NH+KVH)*64) return;
    int i    = idx & 63;
    int rest = idx >> 6;
    int head = rest % (NH+KVH);
    int bl   = rest / (NH+KVH);
    float p   = (float)pos[bl];
    float ang = p * g_invf[i];
    float r   = (float)fmod((double)ang, 6.283185307179586);
    float s, c;
    sincosf(r, &s, &c);          // sin first, cos second
    float* ptr = (head < NH) ? (q + ((size_t)bl*NH + head)*DD)
                             : (k + ((size_t)bl*KVH + (head-NH))*DD);
    float x1 = ptr[i], x2 = ptr[i+64];
    ptr[i]    = x1*c - x2*s;
    ptr[i+64] = x2*c + x1*s;
}

// ---------------- per-position rank within its state ------------------------
__global__ void rank_kernel(const int* __restrict__ sid, int* __restrict__ rank)
{
    __shared__ int s[LL];
    int b = blockIdx.x, t = threadIdx.x;
    s[t]        = sid[(size_t)b*LL + t];
    s[t + 1024] = sid[(size_t)b*LL + t + 1024];
    __syncthreads();
    int l1 = t, l2 = t + 1024;
    int me1 = s[l1], me2 = s[l2];
    int c1 = 0, c2 = 0;
    for (int j = 0; j < LL; j++) {
        int sj = s[j];
        c1 += (j <= l1 && sj == me1);
        c2 += (j <= l2 && sj == me2);
    }
    rank[(size_t)b*LL + l1] = c1 - 1;
    rank[(size_t)b*LL + l2] = c2 - 1;
}

// ---------------- flash attention: 64 q-rows x 64-key tiles -----------------
#define ATTN_SMEM_BYTES 88064

__global__ __launch_bounds__(256, 2) void attn_kernel(
    const float* __restrict__ q, const float* __restrict__ k,
    const float* __restrict__ v, const int* __restrict__ sid,
    const int* __restrict__ rank, float* __restrict__ o)
{
    extern __shared__ float sm[];
    float* QsT   = sm;
    float* KVs   = sm + 128*68;
    float* Ss    = KVs + 128*68;
    float* m_s   = Ss + 64*65;
    float* l_s   = m_s + 64;
    float* fac_s = l_s + 64;
    int* sidq  = (int*)(fac_s + 64);
    int* rankq = sidq + 64;
    int* sidk  = rankq + 64;
    int* rankk = sidk + 64;

    int qt = blockIdx.x, h = blockIdx.y, b = blockIdx.z;
    int kvh  = h >> 2;
    int tid  = threadIdx.x;
    int lane = tid & 31, wid = tid >> 5;
    int tx   = tid & 15, ty  = tid >> 4;
    int q0   = qt * 64;

    const float* qbase = q + ((size_t)(b*LL + q0)*NH + h)*DD;
    for (int i = tid; i < 64*128; i += 256) {
        int r = i >> 7, d = i & 127;
        QsT[d*68 + r] = qbase[(size_t)r*HD + d] * 0.08838834764831845f;
    }
    if (tid < 64) {
        m_s[tid] = -1e30f; l_s[tid] = 0.f;
        sidq[tid]  = sid[(size_t)b*LL + q0 + tid];
        rankq[tid] = rank[(size_t)b*LL + q0 + tid];
    }
    float o_acc[4][8];
    #pragma unroll
    for (int i = 0; i < 4; i++)
        #pragma unroll
        for (int c = 0; c < 8; c++) o_acc[i][c] = 0.f;

    for (int kt = 0; kt <= qt; kt++) {
        int k0 = kt * 64;
        __syncthreads();
        const float* kbase = k + ((size_t)(b*LL + k0)*KVH + kvh)*DD;
        for (int i = tid; i < 64*128; i += 256) {
            int r = i >> 7, d = i & 127;
            KVs[d*68 + r] = kbase[(size_t)r*KVD + d];
        }
        if (tid < 64) {
            sidk[tid]  = sid[(size_t)b*LL + k0 + tid];
            rankk[tid] = rank[(size_t)b*LL + k0 + tid];
        }
        __syncthreads();

        float acc[4][4];
        #pragma unroll
        for (int i = 0; i < 4; i++)
            #pragma unroll
            for (int j = 0; j < 4; j++) acc[i][j] = 0.f;
        #pragma unroll 8
        for (int d = 0; d < 128; d++) {
            float4 a  = *(const float4*)(QsT + d*68 + ty*4);
            float4 bb = *(const float4*)(KVs + d*68 + tx*4);
            float av[4] = {a.x, a.y, a.z, a.w};
            float bv[4] = {bb.x, bb.y, bb.z, bb.w};
            #pragma unroll
            for (int i = 0; i < 4; i++)
                #pragma unroll
                for (int j = 0; j < 4; j++)
                    acc[i][j] = fmaf(av[i], bv[j], acc[i][j]);
        }
        #pragma unroll
        for (int i = 0; i < 4; i++) {
            int qi = ty*4 + i;
            #pragma unroll
            for (int j = 0; j < 4; j++) {
                int kj = tx*4 + j;
                bool ok = (k0 + kj <= q0 + qi) && (sidk[kj] == sidq[qi])
                          && (rankq[qi] - rankk[kj] <= WIN);
                Ss[qi*65 + kj] = ok ? acc[i][j] : -1e30f;
            }
        }
        __syncthreads();

        #pragma unroll
        for (int rr = 0; rr < 8; rr++) {
            int r = wid*8 + rr;
            float s1 = Ss[r*65 + lane];
            float s2 = Ss[r*65 + 32 + lane];
            float mx = fmaxf(s1, s2);
            #pragma unroll
            for (int off = 16; off > 0; off >>= 1)
                mx = fmaxf(mx, __shfl_xor_sync(0xffffffffu, mx, off));
            float mold = m_s[r];
            float mnew = fmaxf(mold, mx);
            float p1 = (s1 > -1e29f) ? __expf(s1 - mnew) : 0.f;
            float p2 = (s2 > -1e29f) ? __expf(s2 - mnew) : 0.f;
            Ss[r*65 + lane]      = p1;
            Ss[r*65 + 32 + lane] = p2;
            float sum = p1 + p2;
            #pragma unroll
            for (int off = 16; off > 0; off >>= 1)
                sum += __shfl_xor_sync(0xffffffffu, sum, off);
            if (lane == 0) {
                float f = __expf(mold - mnew);
                fac_s[r] = f;
                m_s[r]   = mnew;
                l_s[r]   = l_s[r]*f + sum;
            }
        }
        const float* vbase = v + ((size_t)(b*LL + k0)*KVH + kvh)*DD;
        for (int i = tid; i < 64*128; i += 256)
            KVs[i] = vbase[(size_t)(i >> 7)*KVD + (i & 127)];
        __syncthreads();

        #pragma unroll
        for (int i = 0; i < 4; i++) {
            float f = fac_s[ty*4 + i];
            #pragma unroll
            for (int c = 0; c < 8; c++) o_acc[i][c] *= f;
        }
        #pragma unroll 2
        for (int j = 0; j < 64; j++) {
            float av[4];
            #pragma unroll
            for (int i = 0; i < 4; i++) av[i] = Ss[(ty*4 + i)*65 + j];
            float4 v0 = *(const float4*)(KVs + j*128 + tx*8);
            float4 v1 = *(const float4*)(KVs + j*128 + tx*8 + 4);
            float bv[8] = {v0.x,v0.y,v0.z,v0.w,v1.x,v1.y,v1.z,v1.w};
            #pragma unroll
            for (int i = 0; i < 4; i++)
                #pragma unroll
                for (int c = 0; c < 8; c++)
                    o_acc[i][c] = fmaf(av[i], bv[c], o_acc[i][c]);
        }
    }

    float* obase = o + ((size_t)(b*LL + q0)*NH + h)*DD;
    #pragma unroll
    for (int i = 0; i < 4; i++) {
        int r = ty*4 + i;
        float invl = 1.0f / l_s[r];
        float* cp = obase + (size_t)r*HD + tx*8;
        #pragma unroll
        for (int c = 0; c < 8; c++) cp[c] = o_acc[i][c] * invl;
    }
}

// ---------------- launch ----------------------------------------------------
extern "C" void kernel_launch(void* const* d_in, const int* in_sizes, int n_in,
                              void* d_out, int out_size)
{
    const float* hs = (const float*)d_in[0];
    const float* Wq = (const float*)d_in[1];
    const float* Wk = (const float*)d_in[2];
    const float* Wv = (const float*)d_in[3];
    const float* Wo = (const float*)d_in[4];
    const int*   sid = (const int*)d_in[5];
    const int*   pos = (const int*)d_in[6];
    float* out = (float*)d_out;

    float *qp, *kp, *vp, *op;
    int* rp;
    cudaGetSymbolAddress((void**)&qp, g_q);
    cudaGetSymbolAddress((void**)&kp, g_k);
    cudaGetSymbolAddress((void**)&vp, g_v);
    cudaGetSymbolAddress((void**)&op, g_o);
    cudaGetSymbolAddress((void**)&rp, g_rank);

    cudaFuncSetAttribute(attn_kernel, cudaFuncAttributeMaxDynamicSharedMemorySize,
                         ATTN_SMEM_BYTES);
    cudaFuncSetAttribute(gemm_tf32, cudaFuncAttributeMaxDynamicSharedMemorySize,
                         GEMM_SMEM_BYTES);

    invf_kernel<<<1, 64>>>();
    gemm_tf32<<<dim3(HD/128,  (BB*LL)/128), 256, GEMM_SMEM_BYTES>>>(hs, Wq, qp, BB*LL, HD,  HID);
    gemm_tf32<<<dim3(KVD/128, (BB*LL)/128), 256, GEMM_SMEM_BYTES>>>(hs, Wk, kp, BB*LL, KVD, HID);
    gemm_tf32<<<dim3(KVD/128, (BB*LL)/128), 256, GEMM_SMEM_BYTES>>>(hs, Wv, vp, BB*LL, KVD, HID);

    int nrope = BB*LL*(NH+KVH)*64;
    rope_kernel<<<(nrope + 255)/256, 256>>>(qp, kp, pos);
    rank_kernel<<<BB, 1024>>>(sid, rp);

    attn_kernel<<<dim3(LL/64, NH, BB), 256, ATTN_SMEM_BYTES>>>(qp, kp, vp, sid, rp, op);

    gemm_tf32<<<dim3(HID/128, (BB*LL)/128), 256, GEMM_SMEM_BYTES>>>(op, Wo, out, BB*LL, HID, HID);
}

// round 16
// speedup vs baseline: 2.2660x; 1.5045x over previous
#include <cuda_runtime.h>
#include <math.h>
#include <stdint.h>

#define BB 2
#define LL 2048
#define HID 2048
#define NH 16
#define KVH 4
#define DD 128
#define HD 2048
#define KVD 512
#define WIN 1024
#define SCALE 0.08838834764831845f

// ---------------- scratch (device globals: no allocation allowed) ----------
__device__ float g_q[BB*LL*HD];
__device__ float g_k[BB*LL*KVD];
__device__ float g_v[BB*LL*KVD];
__device__ float g_o[BB*LL*HD];
__device__ int   g_rank[BB*LL];
__device__ float g_invf[64];

// ---------------- inv_freq precompute ---------------------------------------
__global__ void invf_kernel() {
    int i = threadIdx.x;
    g_invf[i] = (float)pow(10000.0, -(double)i / 64.0);
}

// ---------------- mma helpers ------------------------------------------------
__device__ __forceinline__ uint32_t f2tf(float x) {
    uint32_t u;
    asm volatile("cvt.rna.tf32.f32 %0, %1;" : "=r"(u) : "f"(x));
    return u;
}
__device__ __forceinline__ void mma_tf32(float* d, const uint32_t* a,
                                         uint32_t b0, uint32_t b1) {
    asm volatile(
        "mma.sync.aligned.m16n8k8.row.col.f32.tf32.tf32.f32 "
        "{%0,%1,%2,%3}, {%4,%5,%6,%7}, {%8,%9}, {%0,%1,%2,%3};"
        : "+f"(d[0]), "+f"(d[1]), "+f"(d[2]), "+f"(d[3])
        : "r"(a[0]), "r"(a[1]), "r"(a[2]), "r"(a[3]), "r"(b0), "r"(b1));
}
__device__ __forceinline__ void cp16(uint32_t dst, const void* src) {
    asm volatile("cp.async.ca.shared.global [%0], [%1], 16;" :: "r"(dst), "l"(src));
}

// ---------------- tf32 tensor-core GEMM: C[M,N] = A[M,K] @ W[N,K]^T ---------
// Block 128x128, 8 warps (4M x 2N), warp tile 32x64, K-chunk 16, 3-stage cp.async.
#define GSTAGES 3
#define GCHUNK  16
#define GSTRIDE 20
#define GSTAGE_FLOATS (2 * 128 * GSTRIDE)
#define GEMM_SMEM_BYTES (GSTAGES * GSTAGE_FLOATS * 4)

__global__ __launch_bounds__(256, 2) void gemm_tf32(
    const float* __restrict__ A, const float* __restrict__ W,
    float* __restrict__ C, int M, int N, int K)
{
    extern __shared__ float sm[];
    int t = threadIdx.x;
    int lane = t & 31, warp = t >> 5;
    int warpM = warp & 3, warpN = warp >> 2;
    int gid = lane >> 2, tig = lane & 3;
    int row0 = blockIdx.y * 128, col0 = blockIdx.x * 128;

    int lrow = t >> 1;
    int lk   = (t & 1) * 8;
    const float* Ag = A + (size_t)(row0 + lrow)*K + lk;
    const float* Wg = W + (size_t)(col0 + lrow)*K + lk;
    uint32_t smem_base = (uint32_t)__cvta_generic_to_shared((void*)sm);
    uint32_t a_dst0 = smem_base + (uint32_t)(lrow*GSTRIDE + lk) * 4;
    uint32_t w_dst0 = a_dst0 + 128*GSTRIDE*4;

    float acc[2][8][4];
    #pragma unroll
    for (int mt = 0; mt < 2; mt++)
        #pragma unroll
        for (int nt = 0; nt < 8; nt++)
            #pragma unroll
            for (int c = 0; c < 4; c++) acc[mt][nt][c] = 0.f;

    int NK = K / GCHUNK;

    #pragma unroll
    for (int s = 0; s < GSTAGES - 1; s++) {
        uint32_t off = (uint32_t)(s * GSTAGE_FLOATS * 4);
        const float* ag = Ag + (size_t)s * GCHUNK;
        const float* wg = Wg + (size_t)s * GCHUNK;
        cp16(a_dst0 + off,      ag);
        cp16(a_dst0 + off + 16, ag + 4);
        cp16(w_dst0 + off,      wg);
        cp16(w_dst0 + off + 16, wg + 4);
        asm volatile("cp.async.commit_group;");
    }

    int rd = 0;
    for (int kt = 0; kt < NK; kt++) {
        asm volatile("cp.async.wait_group %0;" :: "n"(GSTAGES - 2));
        __syncthreads();

        const float* As = sm + rd * GSTAGE_FLOATS;
        const float* Ws = As + 128*GSTRIDE;

        int kn = kt + GSTAGES - 1;
        if (kn < NK) {
            int wr = (rd == 0) ? (GSTAGES - 1) : (rd - 1);
            uint32_t off = (uint32_t)(wr * GSTAGE_FLOATS * 4);
            const float* ag = Ag + (size_t)kn * GCHUNK;
            const float* wg = Wg + (size_t)kn * GCHUNK;
            cp16(a_dst0 + off,      ag);
            cp16(a_dst0 + off + 16, ag + 4);
            cp16(w_dst0 + off,      wg);
            cp16(w_dst0 + off + 16, wg + 4);
            asm volatile("cp.async.commit_group;");
        }

        #pragma unroll
        for (int g = 0; g < 2; g++) {
            uint32_t afr[2][4];
            #pragma unroll
            for (int mt = 0; mt < 2; mt++) {
                const float* ab = As + (warpM*32 + mt*16 + gid)*GSTRIDE + g*8;
                afr[mt][0] = f2tf(ab[tig]);
                afr[mt][1] = f2tf(ab[8*GSTRIDE + tig]);
                afr[mt][2] = f2tf(ab[tig + 4]);
                afr[mt][3] = f2tf(ab[8*GSTRIDE + tig + 4]);
            }
            #pragma unroll
            for (int nt = 0; nt < 8; nt++) {
                const float* bb = Ws + (warpN*64 + nt*8 + gid)*GSTRIDE + g*8;
                uint32_t b0 = f2tf(bb[tig]);
                uint32_t b1 = f2tf(bb[tig + 4]);
                mma_tf32(acc[0][nt], afr[0], b0, b1);
                mma_tf32(acc[1][nt], afr[1], b0, b1);
            }
        }
        rd = (rd + 1 == GSTAGES) ? 0 : rd + 1;
    }

    #pragma unroll
    for (int mt = 0; mt < 2; mt++) {
        int r = row0 + warpM*32 + mt*16 + gid;
        #pragma unroll
        for (int nt = 0; nt < 8; nt++) {
            int c = col0 + warpN*64 + nt*8 + tig*2;
            *(float2*)(C + (size_t)r*N + c) =
                make_float2(acc[mt][nt][0], acc[mt][nt][1]);
            *(float2*)(C + (size_t)(r+8)*N + c) =
                make_float2(acc[mt][nt][2], acc[mt][nt][3]);
        }
    }
}

// ---------------- RoPE (in place on q and k) --------------------------------
__global__ void rope_kernel(float* __restrict__ q, float* __restrict__ k,
                            const int* __restrict__ pos)
{
    int idx = blockIdx.x * 256 + threadIdx.x;
    if (idx >= BB*LL*(NH+KVH)*64) return;
    int i    = idx & 63;
    int rest = idx >> 6;
    int head = rest % (NH+KVH);
    int bl   = rest / (NH+KVH);
    float p   = (float)pos[bl];
    float ang = p * g_invf[i];
    float r   = (float)fmod((double)ang, 6.283185307179586);
    float s, c;
    sincosf(r, &s, &c);          // sin first, cos second
    float* ptr = (head < NH) ? (q + ((size_t)bl*NH + head)*DD)
                             : (k + ((size_t)bl*KVH + (head-NH))*DD);
    float x1 = ptr[i], x2 = ptr[i+64];
    ptr[i]    = x1*c - x2*s;
    ptr[i+64] = x2*c + x1*s;
}

// ---------------- per-position rank within its state ------------------------
__global__ void rank_kernel(const int* __restrict__ sid, int* __restrict__ rank)
{
    __shared__ int s[LL];
    int b = blockIdx.x, t = threadIdx.x;
    s[t]        = sid[(size_t)b*LL + t];
    s[t + 1024] = sid[(size_t)b*LL + t + 1024];
    __syncthreads();
    int l1 = t, l2 = t + 1024;
    int me1 = s[l1], me2 = s[l2];
    int c1 = 0, c2 = 0;
    for (int j = 0; j < LL; j++) {
        int sj = s[j];
        c1 += (j <= l1 && sj == me1);
        c2 += (j <= l2 && sj == me2);
    }
    rank[(size_t)b*LL + l1] = c1 - 1;
    rank[(size_t)b*LL + l2] = c2 - 1;
}

// ---------------- tensor-core flash attention: 64q x 64k tiles ---------------
// smem floats: Qs 64*132=8448 | KVs max(64*132, 128*68)=8704 | Ss 64*68=4352
//            | m,l,fac 3*64 | sid/rank q/k 4*64  => 21952 floats = 87808 B
#define ATTN_SMEM_BYTES 87808

__global__ __launch_bounds__(256, 2) void attn_tc(
    const float* __restrict__ q, const float* __restrict__ k,
    const float* __restrict__ v, const int* __restrict__ sid,
    const int* __restrict__ rank, float* __restrict__ o)
{
    extern __shared__ float sm[];
    float* Qs    = sm;                 // [64][132] row-major, pre-scaled
    float* KVs   = sm + 8448;          // K: [64][132] row-major / V^T: [128][68]
    float* Ss    = sm + 17152;         // [64][68] scores / probs
    float* m_s   = sm + 21504;
    float* l_s   = m_s + 64;
    float* fac_s = l_s + 64;
    int* sidq  = (int*)(fac_s + 64);
    int* rankq = sidq + 64;
    int* sidk  = rankq + 64;
    int* rankk = sidk + 64;

    int qt = blockIdx.x, h = blockIdx.y, b = blockIdx.z;
    int kvh  = h >> 2;
    int tid  = threadIdx.x;
    int lane = tid & 31, wid = tid >> 5;
    int warpM = wid & 3, warpN = wid >> 2;     // 4m x 2n
    int gid = lane >> 2, tig = lane & 3;
    int q0 = qt * 64;

    // Q tile [64][128] scaled, row-major stride 132
    const float* qbase = q + ((size_t)(b*LL + q0)*NH + h)*DD;
    for (int i = tid; i < 64*32; i += 256) {
        int r = i >> 5, c4 = (i & 31) * 4;
        float4 xv = *(const float4*)(qbase + (size_t)r*HD + c4);
        float* dst = Qs + r*132 + c4;
        dst[0] = xv.x*SCALE; dst[1] = xv.y*SCALE; dst[2] = xv.z*SCALE; dst[3] = xv.w*SCALE;
    }
    if (tid < 64) {
        m_s[tid] = -1e30f; l_s[tid] = 0.f;
        sidq[tid]  = sid[(size_t)b*LL + q0 + tid];
        rankq[tid] = rank[(size_t)b*LL + q0 + tid];
    }

    float oacc[8][4];
    #pragma unroll
    for (int nt = 0; nt < 8; nt++)
        #pragma unroll
        for (int c = 0; c < 4; c++) oacc[nt][c] = 0.f;

    int r0 = warpM*16 + gid;    // this thread's S/O rows: r0 and r0+8

    for (int kt = 0; kt <= qt; kt++) {
        int k0 = kt * 64;
        __syncthreads();  // prev PV done before overwriting KVs/Ss
        const float* kbase = k + ((size_t)(b*LL + k0)*KVH + kvh)*DD;
        for (int i = tid; i < 64*32; i += 256) {
            int r = i >> 5, c4 = (i & 31) * 4;
            float4 xv = *(const float4*)(kbase + (size_t)r*KVD + c4);
            float* dst = KVs + r*132 + c4;
            dst[0] = xv.x; dst[1] = xv.y; dst[2] = xv.z; dst[3] = xv.w;
        }
        if (tid < 64) {
            sidk[tid]  = sid[(size_t)b*LL + k0 + tid];
            rankk[tid] = rank[(size_t)b*LL + k0 + tid];
        }
        __syncthreads();

        // S = Q @ K^T via tf32 mma: warp tile 16x32
        float sacc[4][4];
        #pragma unroll
        for (int nt = 0; nt < 4; nt++)
            #pragma unroll
            for (int c = 0; c < 4; c++) sacc[nt][c] = 0.f;
        const float* Arow = Qs + r0*132;
        #pragma unroll
        for (int kc = 0; kc < 16; kc++) {
            uint32_t af[4];
            const float* ab = Arow + kc*8;
            af[0] = f2tf(ab[tig]);
            af[1] = f2tf(ab[8*132 + tig]);
            af[2] = f2tf(ab[tig + 4]);
            af[3] = f2tf(ab[8*132 + tig + 4]);
            #pragma unroll
            for (int nt = 0; nt < 4; nt++) {
                const float* bb = KVs + (warpN*32 + nt*8 + gid)*132 + kc*8;
                mma_tf32(sacc[nt], af, f2tf(bb[tig]), f2tf(bb[tig + 4]));
            }
        }

        // masked write S -> Ss
        int sq0 = sidq[r0], sq1 = sidq[r0+8];
        int rq0 = rankq[r0], rq1 = rankq[r0+8];
        #pragma unroll
        for (int nt = 0; nt < 4; nt++) {
            int cbase = warpN*32 + nt*8 + tig*2;
            #pragma unroll
            for (int j = 0; j < 2; j++) {
                int c = cbase + j;
                bool okA = (k0 + c <= q0 + r0)   && (sidk[c] == sq0) && (rq0 - rankk[c] <= WIN);
                bool okB = (k0 + c <= q0 + r0+8) && (sidk[c] == sq1) && (rq1 - rankk[c] <= WIN);
                Ss[r0*68 + c]     = okA ? sacc[nt][j]   : -1e30f;
                Ss[(r0+8)*68 + c] = okB ? sacc[nt][2+j] : -1e30f;
            }
        }
        __syncthreads();

        // online softmax: warp wid owns rows wid*8 .. +7
        #pragma unroll
        for (int rr = 0; rr < 8; rr++) {
            int r = wid*8 + rr;
            float s1 = Ss[r*68 + lane];
            float s2 = Ss[r*68 + 32 + lane];
            float mx = fmaxf(s1, s2);
            #pragma unroll
            for (int off = 16; off > 0; off >>= 1)
                mx = fmaxf(mx, __shfl_xor_sync(0xffffffffu, mx, off));
            float mold = m_s[r];
            float mnew = fmaxf(mold, mx);
            float p1 = (s1 > -1e29f) ? __expf(s1 - mnew) : 0.f;
            float p2 = (s2 > -1e29f) ? __expf(s2 - mnew) : 0.f;
            Ss[r*68 + lane]      = p1;
            Ss[r*68 + 32 + lane] = p2;
            float sum = p1 + p2;
            #pragma unroll
            for (int off = 16; off > 0; off >>= 1)
                sum += __shfl_xor_sync(0xffffffffu, sum, off);
            if (lane == 0) {
                float f = __expf(mold - mnew);
                fac_s[r] = f;
                m_s[r]   = mnew;
                l_s[r]   = l_s[r]*f + sum;
            }
        }

        // V^T into KVs [128][68] (K reads finished before the post-S sync)
        const float* vbase = v + ((size_t)(b*LL + k0)*KVH + kvh)*DD;
        for (int i = tid; i < 64*128; i += 256)
            KVs[(i & 127)*68 + (i >> 7)] = vbase[(size_t)(i >> 7)*KVD + (i & 127)];
        __syncthreads();

        // rescale O accs, then O += P @ V via tf32 mma (warp tile 16x64)
        float f0 = fac_s[r0], f1 = fac_s[r0+8];
        #pragma unroll
        for (int nt = 0; nt < 8; nt++) {
            oacc[nt][0] *= f0; oacc[nt][1] *= f0;
            oacc[nt][2] *= f1; oacc[nt][3] *= f1;
        }
        const float* Prow = Ss + r0*68;
        #pragma unroll
        for (int kc = 0; kc < 8; kc++) {
            uint32_t af[4];
            const float* ab = Prow + kc*8;
            af[0] = f2tf(ab[tig]);
            af[1] = f2tf(ab[8*68 + tig]);
            af[2] = f2tf(ab[tig + 4]);
            af[3] = f2tf(ab[8*68 + tig + 4]);
            #pragma unroll
            for (int nt = 0; nt < 8; nt++) {
                const float* bb = KVs + (warpN*64 + nt*8 + gid)*68 + kc*8;
                mma_tf32(oacc[nt], af, f2tf(bb[tig]), f2tf(bb[tig + 4]));
            }
        }
    }

    // epilogue: normalize and store
    float invl0 = 1.0f / l_s[r0];
    float invl1 = 1.0f / l_s[r0 + 8];
    float* ob0 = o + ((size_t)(b*LL + q0 + r0)*NH + h)*DD;
    float* ob1 = o + ((size_t)(b*LL + q0 + r0 + 8)*NH + h)*DD;
    #pragma unroll
    for (int nt = 0; nt < 8; nt++) {
        int d = warpN*64 + nt*8 + tig*2;
        *(float2*)(ob0 + d) = make_float2(oacc[nt][0]*invl0, oacc[nt][1]*invl0);
        *(float2*)(ob1 + d) = make_float2(oacc[nt][2]*invl1, oacc[nt][3]*invl1);
    }
}

// ---------------- launch ----------------------------------------------------
extern "C" void kernel_launch(void* const* d_in, const int* in_sizes, int n_in,
                              void* d_out, int out_size)
{
    const float* hs = (const float*)d_in[0];
    const float* Wq = (const float*)d_in[1];
    const float* Wk = (const float*)d_in[2];
    const float* Wv = (const float*)d_in[3];
    const float* Wo = (const float*)d_in[4];
    const int*   sid = (const int*)d_in[5];
    const int*   pos = (const int*)d_in[6];
    float* out = (float*)d_out;

    float *qp, *kp, *vp, *op;
    int* rp;
    cudaGetSymbolAddress((void**)&qp, g_q);
    cudaGetSymbolAddress((void**)&kp, g_k);
    cudaGetSymbolAddress((void**)&vp, g_v);
    cudaGetSymbolAddress((void**)&op, g_o);
    cudaGetSymbolAddress((void**)&rp, g_rank);

    cudaFuncSetAttribute(attn_tc, cudaFuncAttributeMaxDynamicSharedMemorySize,
                         ATTN_SMEM_BYTES);
    cudaFuncSetAttribute(gemm_tf32, cudaFuncAttributeMaxDynamicSharedMemorySize,
                         GEMM_SMEM_BYTES);

    invf_kernel<<<1, 64>>>();
    gemm_tf32<<<dim3(HD/128,  (BB*LL)/128), 256, GEMM_SMEM_BYTES>>>(hs, Wq, qp, BB*LL, HD,  HID);
    gemm_tf32<<<dim3(KVD/128, (BB*LL)/128), 256, GEMM_SMEM_BYTES>>>(hs, Wk, kp, BB*LL, KVD, HID);
    gemm_tf32<<<dim3(KVD/128, (BB*LL)/128), 256, GEMM_SMEM_BYTES>>>(hs, Wv, vp, BB*LL, KVD, HID);

    int nrope = BB*LL*(NH+KVH)*64;
    rope_kernel<<<(nrope + 255)/256, 256>>>(qp, kp, pos);
    rank_kernel<<<BB, 1024>>>(sid, rp);

    attn_tc<<<dim3(LL/64, NH, BB), 256, ATTN_SMEM_BYTES>>>(qp, kp, vp, sid, rp, op);

    gemm_tf32<<<dim3(HID/128, (BB*LL)/128), 256, GEMM_SMEM_BYTES>>>(op, Wo, out, BB*LL, HID, HID);
}